// round 13
// baseline (speedup 1.0000x reference)
#include <cuda_runtime.h>
#include <cstdint>
#include <cstddef>

typedef unsigned long long u64;

// ---- packed f32x2 helpers (Blackwell sm_103a) ----
#define FMA2(d, a, b, c) asm("fma.rn.f32x2 %0, %1, %2, %3;" : "=l"(d) : "l"(a), "l"(b), "l"(c))
#define MUL2(d, a, b)    asm("mul.rn.f32x2 %0, %1, %2;"     : "=l"(d) : "l"(a), "l"(b))
#define ADD2(d, a, b)    asm("add.rn.f32x2 %0, %1, %2;"     : "=l"(d) : "l"(a), "l"(b))

__device__ __forceinline__ u64 pack2(float lo, float hi) {
    u64 r; asm("mov.b64 %0, {%1, %2};" : "=l"(r) : "f"(lo), "f"(hi)); return r;
}
__device__ __forceinline__ float2 unpack2(u64 v) {
    float2 r; asm("mov.b64 {%0, %1}, %2;" : "=f"(r.x), "=f"(r.y) : "l"(v)); return r;
}
__device__ __forceinline__ void stg_cs_v4(float* p, float4 v) {
    asm volatile("st.global.cs.v4.f32 [%0], {%1, %2, %3, %4};"
                 :: "l"(p), "f"(v.x), "f"(v.y), "f"(v.z), "f"(v.w) : "memory");
}
__device__ __forceinline__ uint32_t smem_u32(const void* p) {
    uint32_t a;
    asm("{ .reg .u64 t; cvta.to.shared.u64 t, %1; cvt.u32.u64 %0, t; }" : "=r"(a) : "l"(p));
    return a;
}
__device__ __forceinline__ void mbar_init(uint32_t mbar, uint32_t cnt) {
    asm volatile("mbarrier.init.shared.b64 [%0], %1;" :: "r"(mbar), "r"(cnt) : "memory");
}
__device__ __forceinline__ void mbar_expect_tx(uint32_t mbar, uint32_t bytes) {
    asm volatile("mbarrier.arrive.expect_tx.shared.b64 _, [%0], %1;" :: "r"(mbar), "r"(bytes) : "memory");
}
__device__ __forceinline__ void bulk_g2s(uint32_t dst, const void* src, uint32_t bytes, uint32_t mbar) {
    asm volatile("cp.async.bulk.shared::cta.global.mbarrier::complete_tx::bytes [%0], [%1], %2, [%3];"
                 :: "r"(dst), "l"(src), "r"(bytes), "r"(mbar) : "memory");
}
__device__ __forceinline__ void mbar_wait(uint32_t mbar, uint32_t parity) {
    asm volatile(
        "{\n\t"
        ".reg .pred P1;\n\t"
        "WL_%=:\n\t"
        "mbarrier.try_wait.parity.acquire.cta.shared::cta.b64 P1, [%0], %1, 0x989680;\n\t"
        "@P1 bra.uni WD_%=;\n\t"
        "bra.uni WL_%=;\n\t"
        "WD_%=:\n\t"
        "}"
        :: "r"(mbar), "r"(parity) : "memory");
}

constexpr int E_DIM = 1024;

// ============================================================================
// Fused: h = x@w1^T + b1 ; q = Pauli-Z cosine strings ; out = q@w2^T + b2
//   q0=c0, q1=c1, q2=c0c2, q3=c1c3, q4=c0c2c4, q5=c1c3c5, q6=c0c2c4c6,
//   q7=c0..c7  with c_i = cos(h_i)
//
// RPB=8: grid 4096 over 592 residency slots (~6.9 blocks/slot) shrinks the
// wave-quantization tail from ~14% (grid 1024 = 1.73 waves) to ~1-7%.
// NSTAGE == NSLOT: both 16KB ring slots primed up front, ZERO refills and
// zero per-stage CTA barriers (each warp waits the mbarriers itself; one
// __syncthreads before the q epilogue). Static smem ~34.5KB -> 4 CTAs/SM.
// ============================================================================
constexpr int RPB     = 8;                   // rows per block
constexpr int SROWS   = 4;                   // rows per stage
constexpr int NSLOT   = 2;                   // == NSTAGE (no refills)
constexpr int NSTAGE  = RPB / SROWS;         // 2
constexpr int STBYTES = SROWS * E_DIM * 4;   // 16384

__global__ void __launch_bounds__(256, 4)
ffq_fused(const float* __restrict__ x,  const float* __restrict__ w1,
          const float* __restrict__ b1, const float* __restrict__ w2,
          const float* __restrict__ b2, float* __restrict__ out, int rows)
{
    __shared__ __align__(128) float xs[NSLOT][SROWS * E_DIM];  // 32 KB
    __shared__ __align__(16) float s_part[RPB][8][8];          // 2 KB
    __shared__ __align__(16) float s_q[RPB][8];                // 256 B
    __shared__ __align__(8) u64 mbar_s[NSLOT];

    const int tid  = threadIdx.x;
    const int warp = tid >> 5;
    const int lane = tid & 31;

    const uint32_t mb0 = smem_u32(&mbar_s[0]);
    const uint32_t xs0 = smem_u32(&xs[0][0]);

    // ---- [A] phase-1 weights: f-pair packed, warp owns 128-wide e-slice ----
    const int e1 = warp * 128 + lane * 4;
    u64 wpk[4][4];
#pragma unroll
    for (int p = 0; p < 4; p++) {
        const float* w0 = w1 + (2 * p)     * E_DIM + e1;
        const float* w1r= w1 + (2 * p + 1) * E_DIM + e1;
#pragma unroll
        for (int e = 0; e < 4; e++)
            wpk[p][e] = pack2(w0[e], w1r[e]);
    }
    const float bf = b1[tid & 7];

    if (tid == 0) {
#pragma unroll
        for (int k = 0; k < NSLOT; k++) mbar_init(mb0 + k * 8, 1);
    }
    __syncthreads();

    const int    block_row0 = blockIdx.x * RPB;
    const float* src = x + (size_t)block_row0 * E_DIM;

    // prime both slots (covers the whole block's x; no refills ever)
    if (tid == 0) {
#pragma unroll
        for (int k = 0; k < NSLOT; k++) {
            mbar_expect_tx(mb0 + k * 8, STBYTES);
            bulk_g2s(xs0 + k * STBYTES, src + (size_t)k * SROWS * E_DIM,
                     STBYTES, mb0 + k * 8);
        }
    }

    const bool hi16 = (lane & 16);
    const bool hi8  = (lane & 8);

#pragma unroll
    for (int s = 0; s < NSTAGE; s++) {
        mbar_wait(mb0 + s * 8, 0);     // per-warp; single use, parity 0

#pragma unroll
        for (int r = 0; r < SROWS; r++) {
            float4 xv = *reinterpret_cast<const float4*>(
                &xs[s][r * E_DIM + e1]);
            u64 xd[4];
            xd[0] = pack2(xv.x, xv.x);
            xd[1] = pack2(xv.y, xv.y);
            xd[2] = pack2(xv.z, xv.z);
            xd[3] = pack2(xv.w, xv.w);

            u64 v0, v1, v2, v3;
            MUL2(v0, xd[0], wpk[0][0]);
            MUL2(v1, xd[0], wpk[1][0]);
            MUL2(v2, xd[0], wpk[2][0]);
            MUL2(v3, xd[0], wpk[3][0]);
#pragma unroll
            for (int e = 1; e < 4; e++) {
                FMA2(v0, xd[e], wpk[0][e], v0);
                FMA2(v1, xd[e], wpk[1][e], v1);
                FMA2(v2, xd[e], wpk[2][e], v2);
                FMA2(v3, xd[e], wpk[3][e], v3);
            }

            // packed value-halving butterfly on 4 u64 pair-accumulators
            {
                u64 s0 = hi16 ? v0 : v2;
                u64 s1 = hi16 ? v1 : v3;
                u64 k0 = hi16 ? v2 : v0;
                u64 k1 = hi16 ? v3 : v1;
                u64 r0 = __shfl_xor_sync(0xffffffffu, s0, 16);
                u64 r1 = __shfl_xor_sync(0xffffffffu, s1, 16);
                ADD2(v0, k0, r0);
                ADD2(v1, k1, r1);
            }
            u64 w;
            {
                u64 sv = hi8 ? v0 : v1;
                u64 kv = hi8 ? v1 : v0;
                u64 rv = __shfl_xor_sync(0xffffffffu, sv, 8);
                ADD2(w, kv, rv);
            }
            {
                u64 rv = __shfl_xor_sync(0xffffffffu, w, 4);
                ADD2(w, w, rv);
                rv = __shfl_xor_sync(0xffffffffu, w, 2);
                ADD2(w, w, rv);
                rv = __shfl_xor_sync(0xffffffffu, w, 1);
                ADD2(w, w, rv);
            }
            if ((lane & 7) == 0) {
                const int p = lane >> 3;
                *reinterpret_cast<u64*>(&s_part[s * SROWS + r][warp][2 * p]) = w;
            }
        }
    }
    __syncthreads();   // all warps done; s_part fully visible

    // ---- [B] q epilogue: 8 rows x 8 f = 64 items (tid < 64) ----
    if (tid < 64) {
        const int r  = tid >> 3;          // 0..7
        const int ff = tid & 7;           // matches bf

        float h = bf;
#pragma unroll
        for (int w = 0; w < 8; w++) h += s_part[r][w][ff];
        float c = __cosf(h);

        const int base = lane & 24;
        float cs[8];
#pragma unroll
        for (int jj = 0; jj < 8; jj++)
            cs[jj] = __shfl_sync(0xffffffffu, c, base + jj);

        float q;
        if (ff == 7) {
            q = cs[0]*cs[1]*cs[2]*cs[3]*cs[4]*cs[5]*cs[6]*cs[7];
        } else {
            q = 1.0f;
#pragma unroll
            for (int jj = 0; jj < 8; jj++)
                if (jj <= ff && ((jj ^ ff) & 1) == 0) q *= cs[jj];
        }
        s_q[r][ff] = q;
    }
    __syncthreads();

    // ---- [C] out tail: w2 f-pairs in regs (loaded after w1 regs die) ----
    const int e2 = tid * 4;
    u64 wp[4][4];
#pragma unroll
    for (int i = 0; i < 4; i++) {
        ulonglong2 v0 = *reinterpret_cast<const ulonglong2*>(w2 + (e2 + i) * 8);
        ulonglong2 v1 = *reinterpret_cast<const ulonglong2*>(w2 + (e2 + i) * 8 + 4);
        wp[i][0] = v0.x; wp[i][1] = v0.y;
        wp[i][2] = v1.x; wp[i][3] = v1.y;
    }
    u64 binit[4];
    {
        float4 bv = *reinterpret_cast<const float4*>(b2 + e2);
        binit[0] = pack2(bv.x, 0.f);
        binit[1] = pack2(bv.y, 0.f);
        binit[2] = pack2(bv.z, 0.f);
        binit[3] = pack2(bv.w, 0.f);
    }

    float* orow = out + (size_t)block_row0 * E_DIM + e2;
#pragma unroll
    for (int r = 0; r < RPB; r++) {
        ulonglong2 qv0 = *reinterpret_cast<const ulonglong2*>(&s_q[r][0]);
        ulonglong2 qv1 = *reinterpret_cast<const ulonglong2*>(&s_q[r][4]);

        float o[4];
#pragma unroll
        for (int i = 0; i < 4; i++) {
            u64 acc = binit[i];
            FMA2(acc, qv0.x, wp[i][0], acc);
            FMA2(acc, qv0.y, wp[i][1], acc);
            FMA2(acc, qv1.x, wp[i][2], acc);
            FMA2(acc, qv1.y, wp[i][3], acc);
            float2 t = unpack2(acc);
            o[i] = t.x + t.y;
        }
        stg_cs_v4(orow, make_float4(o[0], o[1], o[2], o[3]));
        orow += E_DIM;
    }
}

extern "C" void kernel_launch(void* const* d_in, const int* in_sizes, int n_in,
                              void* d_out, int out_size) {
    const float* x  = (const float*)d_in[0];
    const float* w1 = (const float*)d_in[1];
    const float* b1 = (const float*)d_in[2];
    const float* w2 = (const float*)d_in[3];
    const float* b2 = (const float*)d_in[4];
    float* out = (float*)d_out;

    const int rows = in_sizes[0] / E_DIM;        // 32768
    ffq_fused<<<rows / RPB, 256>>>(x, w1, b1, w2, b2, out, rows);  // 4096 blocks
}

// round 14
// speedup vs baseline: 1.1174x; 1.1174x over previous
#include <cuda_runtime.h>
#include <cstdint>
#include <cstddef>

typedef unsigned long long u64;

// ---- packed f32x2 helpers (Blackwell sm_103a) ----
#define FMA2(d, a, b, c) asm("fma.rn.f32x2 %0, %1, %2, %3;" : "=l"(d) : "l"(a), "l"(b), "l"(c))
#define MUL2(d, a, b)    asm("mul.rn.f32x2 %0, %1, %2;"     : "=l"(d) : "l"(a), "l"(b))
#define ADD2(d, a, b)    asm("add.rn.f32x2 %0, %1, %2;"     : "=l"(d) : "l"(a), "l"(b))

__device__ __forceinline__ u64 pack2(float lo, float hi) {
    u64 r; asm("mov.b64 %0, {%1, %2};" : "=l"(r) : "f"(lo), "f"(hi)); return r;
}
__device__ __forceinline__ float2 unpack2(u64 v) {
    float2 r; asm("mov.b64 {%0, %1}, %2;" : "=f"(r.x), "=f"(r.y) : "l"(v)); return r;
}
// volatile LDGs (defeat hoisting; L1-resident across tiles)
__device__ __forceinline__ ulonglong2 ldg_v2u64(const float* p) {
    ulonglong2 v;
    asm volatile("ld.global.nc.v2.b64 {%0, %1}, [%2];"
                 : "=l"(v.x), "=l"(v.y) : "l"(p));
    return v;
}
__device__ __forceinline__ float2 ldg_f2(const float* p) {
    float2 v;
    asm volatile("ld.global.nc.v2.f32 {%0, %1}, [%2];"
                 : "=f"(v.x), "=f"(v.y) : "l"(p));
    return v;
}
__device__ __forceinline__ void stg_cs_v2(float* p, float a, float b) {
    asm volatile("st.global.cs.v2.f32 [%0], {%1, %2};"
                 :: "l"(p), "f"(a), "f"(b) : "memory");
}
__device__ __forceinline__ uint32_t smem_u32(const void* p) {
    uint32_t a;
    asm("{ .reg .u64 t; cvta.to.shared.u64 t, %1; cvt.u32.u64 %0, t; }" : "=r"(a) : "l"(p));
    return a;
}
__device__ __forceinline__ void mbar_init(uint32_t mbar, uint32_t cnt) {
    asm volatile("mbarrier.init.shared.b64 [%0], %1;" :: "r"(mbar), "r"(cnt) : "memory");
}
__device__ __forceinline__ void mbar_expect_tx(uint32_t mbar, uint32_t bytes) {
    asm volatile("mbarrier.arrive.expect_tx.shared.b64 _, [%0], %1;" :: "r"(mbar), "r"(bytes) : "memory");
}
__device__ __forceinline__ void bulk_g2s(uint32_t dst, const void* src, uint32_t bytes, uint32_t mbar) {
    asm volatile("cp.async.bulk.shared::cta.global.mbarrier::complete_tx::bytes [%0], [%1], %2, [%3];"
                 :: "r"(dst), "l"(src), "r"(bytes), "r"(mbar) : "memory");
}
__device__ __forceinline__ void mbar_wait(uint32_t mbar, uint32_t parity) {
    asm volatile(
        "{\n\t"
        ".reg .pred P1;\n\t"
        "WL_%=:\n\t"
        "mbarrier.try_wait.parity.acquire.cta.shared::cta.b64 P1, [%0], %1, 0x989680;\n\t"
        "@P1 bra.uni WD_%=;\n\t"
        "bra.uni WL_%=;\n\t"
        "WD_%=:\n\t"
        "}"
        :: "r"(mbar), "r"(parity) : "memory");
}

constexpr int E_DIM = 1024;

// ============================================================================
// PERSISTENT fused kernel. Each CTA grid-strides over 8-row tiles:
//   tile t: [A] 2 TMA stages (4 rows each) -> butterfly -> s_part
//           [B] q epilogue (tid<64) -> s_q
//           [C] out tail, two half-column passes (w2 reloaded per pass,
//               volatile -> L1-resident; peak live regs stay <= 64)
// The TMA ring flows CONTINUOUSLY across tiles: the refill issued at tile
// t's stage-s sync targets tile (t+GRID)'s stage s, so reads stream through
// the epilogue and no tile ever cold-starts. w1 stays in regs for the whole
// kernel. Tiles/CTA ~= 6.92 -> <=1-tile imbalance (vs 14% wave tail @ R11).
//   q0=c0, q1=c1, q2=c0c2, q3=c1c3, q4=c0c2c4, q5=c1c3c5, q6=c0c2c4c6,
//   q7=c0..c7  with c_i = cos(h_i)
// ============================================================================
constexpr int RPB     = 8;                   // rows per tile
constexpr int SROWS   = 4;                   // rows per stage
constexpr int NSLOT   = 2;                   // ring depth == stages/tile
constexpr int STBYTES = SROWS * E_DIM * 4;   // 16384

__global__ void __launch_bounds__(256, 4)
ffq_fused(const float* __restrict__ x,  const float* __restrict__ w1,
          const float* __restrict__ b1, const float* __restrict__ w2,
          const float* __restrict__ b2, float* __restrict__ out, int ntiles)
{
    __shared__ __align__(128) float xs[NSLOT][SROWS * E_DIM];  // 32 KB
    __shared__ __align__(16) float s_part[RPB][8][8];          // 2 KB
    __shared__ __align__(16) float s_q[RPB][8];                // 256 B
    __shared__ __align__(8) u64 mbar_s[NSLOT];

    const int tid  = threadIdx.x;
    const int warp = tid >> 5;
    const int lane = tid & 31;
    const int GRID = gridDim.x;

    const uint32_t mb0 = smem_u32(&mbar_s[0]);
    const uint32_t xs0 = smem_u32(&xs[0][0]);

    // w1 f-pair packed, warp owns 128-wide e-slice — loaded ONCE, persists
    const int e1 = warp * 128 + lane * 4;
    u64 wpk[4][4];
#pragma unroll
    for (int p = 0; p < 4; p++) {
        const float* w0 = w1 + (2 * p)     * E_DIM + e1;
        const float* w1r= w1 + (2 * p + 1) * E_DIM + e1;
#pragma unroll
        for (int e = 0; e < 4; e++)
            wpk[p][e] = pack2(w0[e], w1r[e]);
    }
    const float bf = b1[tid & 7];

    if (tid == 0) {
#pragma unroll
        for (int k = 0; k < NSLOT; k++) mbar_init(mb0 + k * 8, 1);
    }
    __syncthreads();

    // prime the ring with this CTA's first tile
    if (tid == 0 && blockIdx.x < ntiles) {
        const float* src = x + (size_t)blockIdx.x * RPB * E_DIM;
#pragma unroll
        for (int k = 0; k < NSLOT; k++) {
            mbar_expect_tx(mb0 + k * 8, STBYTES);
            bulk_g2s(xs0 + k * STBYTES, src + (size_t)k * SROWS * E_DIM,
                     STBYTES, mb0 + k * 8);
        }
    }

    const bool hi16 = (lane & 16);
    const bool hi8  = (lane & 8);

    int it = 0;
    for (int t = blockIdx.x; t < ntiles; t += GRID, it++) {
        const int parity = it & 1;

        // ================= [A] two TMA stages =================
#pragma unroll
        for (int s = 0; s < NSLOT; s++) {
            mbar_wait(mb0 + s * 8, parity);

#pragma unroll
            for (int r = 0; r < SROWS; r++) {
                float4 xv = *reinterpret_cast<const float4*>(
                    &xs[s][r * E_DIM + e1]);
                u64 xd[4];
                xd[0] = pack2(xv.x, xv.x);
                xd[1] = pack2(xv.y, xv.y);
                xd[2] = pack2(xv.z, xv.z);
                xd[3] = pack2(xv.w, xv.w);

                u64 v0, v1, v2, v3;
                MUL2(v0, xd[0], wpk[0][0]);
                MUL2(v1, xd[0], wpk[1][0]);
                MUL2(v2, xd[0], wpk[2][0]);
                MUL2(v3, xd[0], wpk[3][0]);
#pragma unroll
                for (int e = 1; e < 4; e++) {
                    FMA2(v0, xd[e], wpk[0][e], v0);
                    FMA2(v1, xd[e], wpk[1][e], v1);
                    FMA2(v2, xd[e], wpk[2][e], v2);
                    FMA2(v3, xd[e], wpk[3][e], v3);
                }

                // packed value-halving butterfly
                {
                    u64 s0 = hi16 ? v0 : v2;
                    u64 s1 = hi16 ? v1 : v3;
                    u64 k0 = hi16 ? v2 : v0;
                    u64 k1 = hi16 ? v3 : v1;
                    u64 r0 = __shfl_xor_sync(0xffffffffu, s0, 16);
                    u64 r1 = __shfl_xor_sync(0xffffffffu, s1, 16);
                    ADD2(v0, k0, r0);
                    ADD2(v1, k1, r1);
                }
                u64 w;
                {
                    u64 sv = hi8 ? v0 : v1;
                    u64 kv = hi8 ? v1 : v0;
                    u64 rv = __shfl_xor_sync(0xffffffffu, sv, 8);
                    ADD2(w, kv, rv);
                }
                {
                    u64 rv = __shfl_xor_sync(0xffffffffu, w, 4);
                    ADD2(w, w, rv);
                    rv = __shfl_xor_sync(0xffffffffu, w, 2);
                    ADD2(w, w, rv);
                    rv = __shfl_xor_sync(0xffffffffu, w, 1);
                    ADD2(w, w, rv);
                }
                if ((lane & 7) == 0) {
                    const int p = lane >> 3;
                    *reinterpret_cast<u64*>(
                        &s_part[s * SROWS + r][warp][2 * p]) = w;
                }
            }
            __syncthreads();   // slot drained; s_part rows committed

            // continuous refill: same slot, same stage, NEXT tile (t+GRID)
            if (tid == 0 && t + GRID < ntiles) {
                mbar_expect_tx(mb0 + s * 8, STBYTES);
                bulk_g2s(xs0 + s * STBYTES,
                         x + ((size_t)(t + GRID) * RPB + s * SROWS) * E_DIM,
                         STBYTES, mb0 + s * 8);
            }
        }

        // ================= [B] q epilogue (tid < 64) =================
        if (tid < 64) {
            const int r  = tid >> 3;
            const int ff = tid & 7;          // == tid & 7, matches bf

            float h = bf;
#pragma unroll
            for (int w = 0; w < 8; w++) h += s_part[r][w][ff];
            float c = __cosf(h);

            const int base = lane & 24;
            float cs[8];
#pragma unroll
            for (int jj = 0; jj < 8; jj++)
                cs[jj] = __shfl_sync(0xffffffffu, c, base + jj);

            float q;
            if (ff == 7) {
                q = cs[0]*cs[1]*cs[2]*cs[3]*cs[4]*cs[5]*cs[6]*cs[7];
            } else {
                q = 1.0f;
#pragma unroll
                for (int jj = 0; jj < 8; jj++)
                    if (jj <= ff && ((jj ^ ff) & 1) == 0) q *= cs[jj];
            }
            s_q[r][ff] = q;
        }
        __syncthreads();

        // ====== [C] out tail: two half-column passes, w2 per pass ======
#pragma unroll
        for (int p = 0; p < 2; p++) {
            const int e2p = p * 512 + tid * 2;   // 2 cols/thread, coalesced
            // w2 rows e2p, e2p+1 (8 floats each, contiguous)
            ulonglong2 wa = ldg_v2u64(w2 + e2p * 8);          // col a, f0..3
            ulonglong2 wb = ldg_v2u64(w2 + e2p * 8 + 4);      // col a, f4..7
            ulonglong2 wc = ldg_v2u64(w2 + (e2p + 1) * 8);    // col b, f0..3
            ulonglong2 wd = ldg_v2u64(w2 + (e2p + 1) * 8 + 4);// col b, f4..7
            float2 bias = ldg_f2(b2 + e2p);

            float* orow = out + (size_t)t * RPB * E_DIM + e2p;
#pragma unroll
            for (int r = 0; r < RPB; r++) {
                ulonglong2 qv0 = *reinterpret_cast<const ulonglong2*>(&s_q[r][0]);
                ulonglong2 qv1 = *reinterpret_cast<const ulonglong2*>(&s_q[r][4]);

                u64 acca, accb;
                MUL2(acca, qv0.x, wa.x);
                FMA2(acca, qv0.y, wa.y, acca);
                FMA2(acca, qv1.x, wb.x, acca);
                FMA2(acca, qv1.y, wb.y, acca);
                MUL2(accb, qv0.x, wc.x);
                FMA2(accb, qv0.y, wc.y, accb);
                FMA2(accb, qv1.x, wd.x, accb);
                FMA2(accb, qv1.y, wd.y, accb);
                float2 ta = unpack2(acca);
                float2 tb = unpack2(accb);
                stg_cs_v2(orow, ta.x + ta.y + bias.x, tb.x + tb.y + bias.y);
                orow += E_DIM;
            }
        }
        // next iteration's s_part writes are fenced by its stage syncs;
        // s_q rewrite happens after those syncs -> no trailing barrier.
    }
}

extern "C" void kernel_launch(void* const* d_in, const int* in_sizes, int n_in,
                              void* d_out, int out_size) {
    const float* x  = (const float*)d_in[0];
    const float* w1 = (const float*)d_in[1];
    const float* b1 = (const float*)d_in[2];
    const float* w2 = (const float*)d_in[3];
    const float* b2 = (const float*)d_in[4];
    float* out = (float*)d_out;

    int nsm = 148;
    cudaDeviceGetAttribute(&nsm, cudaDevAttrMultiProcessorCount, 0);
    const int grid = 4 * nsm;                    // persistent: 4 CTAs/SM

    const int rows   = in_sizes[0] / E_DIM;      // 32768
    const int ntiles = rows / RPB;               // 4096
    ffq_fused<<<grid, 256>>>(x, w1, b1, w2, b2, out, ntiles);
}

// round 15
// speedup vs baseline: 1.5554x; 1.3920x over previous
#include <cuda_runtime.h>
#include <cstdint>
#include <cstddef>

typedef unsigned long long u64;

// ---- packed f32x2 helpers (Blackwell sm_103a) ----
#define FMA2(d, a, b, c) asm("fma.rn.f32x2 %0, %1, %2, %3;" : "=l"(d) : "l"(a), "l"(b), "l"(c))
#define MUL2(d, a, b)    asm("mul.rn.f32x2 %0, %1, %2;"     : "=l"(d) : "l"(a), "l"(b))
#define ADD2(d, a, b)    asm("add.rn.f32x2 %0, %1, %2;"     : "=l"(d) : "l"(a), "l"(b))

__device__ __forceinline__ u64 pack2(float lo, float hi) {
    u64 r; asm("mov.b64 %0, {%1, %2};" : "=l"(r) : "f"(lo), "f"(hi)); return r;
}
__device__ __forceinline__ float2 unpack2(u64 v) {
    float2 r; asm("mov.b64 {%0, %1}, %2;" : "=f"(r.x), "=f"(r.y) : "l"(v)); return r;
}
__device__ __forceinline__ void stg_cs_v4(float* p, float4 v) {
    asm volatile("st.global.cs.v4.f32 [%0], {%1, %2, %3, %4};"
                 :: "l"(p), "f"(v.x), "f"(v.y), "f"(v.z), "f"(v.w) : "memory");
}
__device__ __forceinline__ uint32_t smem_u32(const void* p) {
    uint32_t a;
    asm("{ .reg .u64 t; cvta.to.shared.u64 t, %1; cvt.u32.u64 %0, t; }" : "=r"(a) : "l"(p));
    return a;
}
__device__ __forceinline__ void mbar_init(uint32_t mbar, uint32_t cnt) {
    asm volatile("mbarrier.init.shared.b64 [%0], %1;" :: "r"(mbar), "r"(cnt) : "memory");
}
__device__ __forceinline__ void mbar_expect_tx(uint32_t mbar, uint32_t bytes) {
    asm volatile("mbarrier.arrive.expect_tx.shared.b64 _, [%0], %1;" :: "r"(mbar), "r"(bytes) : "memory");
}
__device__ __forceinline__ void bulk_g2s(uint32_t dst, const void* src, uint32_t bytes, uint32_t mbar) {
    asm volatile("cp.async.bulk.shared::cta.global.mbarrier::complete_tx::bytes [%0], [%1], %2, [%3];"
                 :: "r"(dst), "l"(src), "r"(bytes), "r"(mbar) : "memory");
}
__device__ __forceinline__ void mbar_wait(uint32_t mbar, uint32_t parity) {
    asm volatile(
        "{\n\t"
        ".reg .pred P1;\n\t"
        "WL_%=:\n\t"
        "mbarrier.try_wait.parity.acquire.cta.shared::cta.b64 P1, [%0], %1, 0x989680;\n\t"
        "@P1 bra.uni WD_%=;\n\t"
        "bra.uni WL_%=;\n\t"
        "WD_%=:\n\t"
        "}"
        :: "r"(mbar), "r"(parity) : "memory");
}

constexpr int E_DIM = 1024;

// ============================================================================
// Fused: h = x@w1^T + b1 ; q = Pauli-Z cosine strings ; out = q@w2^T + b2
//   q0=c0, q1=c1, q2=c0c2, q3=c1c3, q4=c0c2c4, q5=c1c3c5, q6=c0c2c4c6,
//   q7=c0..c7  with c_i = cos(h_i)
//
// R11 internals verbatim (2-slot TMA ring, per-stage __syncthreads, packed
// f-pair butterfly, deferred q, w2-in-regs tail), but ONE-WAVE BALANCED
// PARTITIONING: grid = 592 = exactly the 4-CTA/SM residency slots; block b
// owns 4-row groups [NG*b/GRID, NG*(b+1)/GRID) -> 13 or 14 groups (52/56
// rows). Wave-tail waste drops from 13.5% (1024 tiles / 592 slots = 1.73
// waves) to ~1.2% (14 vs 13.84 groups).
// ============================================================================
constexpr int SROWS   = 4;                   // rows per pipeline stage
constexpr int NSLOT   = 2;                   // ring depth
constexpr int MAXR    = 56;                  // max rows per block (14 groups)
constexpr int STBYTES = SROWS * E_DIM * 4;   // 16384

__global__ void __launch_bounds__(256, 4)
ffq_fused(const float* __restrict__ x,  const float* __restrict__ w1,
          const float* __restrict__ b1, const float* __restrict__ w2,
          const float* __restrict__ b2, float* __restrict__ out, int ngroups)
{
    __shared__ __align__(128) float xs[NSLOT][SROWS * E_DIM];  // 32 KB ring
    __shared__ __align__(16) float s_part[MAXR][8][8];         // 14 KB
    __shared__ __align__(16) float s_q[MAXR][8];               // 1.75 KB
    __shared__ __align__(8) u64 mbar_s[NSLOT];

    const int tid  = threadIdx.x;
    const int warp = tid >> 5;
    const int lane = tid & 31;

    const uint32_t mb0 = smem_u32(&mbar_s[0]);
    const uint32_t xs0 = smem_u32(&xs[0][0]);

    // balanced group range for this block
    const int g0     = (int)(((long long)ngroups * blockIdx.x)       / gridDim.x);
    const int g1     = (int)(((long long)ngroups * (blockIdx.x + 1)) / gridDim.x);
    const int nstage = g1 - g0;              // 13 or 14
    const int nrows  = nstage * SROWS;       // 52 or 56
    const int block_row0 = g0 * SROWS;

    // ---- [A] phase-1 weights: f-pair packed, warp owns 128-wide e-slice ----
    const int e1 = warp * 128 + lane * 4;
    u64 wpk[4][4];
#pragma unroll
    for (int p = 0; p < 4; p++) {
        const float* w0 = w1 + (2 * p)     * E_DIM + e1;
        const float* w1r= w1 + (2 * p + 1) * E_DIM + e1;
#pragma unroll
        for (int e = 0; e < 4; e++)
            wpk[p][e] = pack2(w0[e], w1r[e]);
    }
    const float bf = b1[tid & 7];

    if (tid == 0) {
#pragma unroll
        for (int k = 0; k < NSLOT; k++) mbar_init(mb0 + k * 8, 1);
    }
    __syncthreads();

    const float* src = x + (size_t)block_row0 * E_DIM;

    // prime the ring
    if (tid == 0) {
#pragma unroll
        for (int k = 0; k < NSLOT; k++) {
            mbar_expect_tx(mb0 + k * 8, STBYTES);
            bulk_g2s(xs0 + k * STBYTES, src + (size_t)k * SROWS * E_DIM,
                     STBYTES, mb0 + k * 8);
        }
    }

    const bool hi16 = (lane & 16);
    const bool hi8  = (lane & 8);

    for (int s = 0; s < nstage; s++) {
        const int slot = s & (NSLOT - 1);
        mbar_wait(mb0 + slot * 8, (s >> 1) & 1);

#pragma unroll
        for (int r = 0; r < SROWS; r++) {
            float4 xv = *reinterpret_cast<const float4*>(
                &xs[slot][r * E_DIM + e1]);
            u64 xd[4];
            xd[0] = pack2(xv.x, xv.x);
            xd[1] = pack2(xv.y, xv.y);
            xd[2] = pack2(xv.z, xv.z);
            xd[3] = pack2(xv.w, xv.w);

            u64 v0, v1, v2, v3;
            MUL2(v0, xd[0], wpk[0][0]);
            MUL2(v1, xd[0], wpk[1][0]);
            MUL2(v2, xd[0], wpk[2][0]);
            MUL2(v3, xd[0], wpk[3][0]);
#pragma unroll
            for (int e = 1; e < 4; e++) {
                FMA2(v0, xd[e], wpk[0][e], v0);
                FMA2(v1, xd[e], wpk[1][e], v1);
                FMA2(v2, xd[e], wpk[2][e], v2);
                FMA2(v3, xd[e], wpk[3][e], v3);
            }

            // packed value-halving butterfly on 4 u64 pair-accumulators
            {
                u64 s0 = hi16 ? v0 : v2;
                u64 s1 = hi16 ? v1 : v3;
                u64 k0 = hi16 ? v2 : v0;
                u64 k1 = hi16 ? v3 : v1;
                u64 r0 = __shfl_xor_sync(0xffffffffu, s0, 16);
                u64 r1 = __shfl_xor_sync(0xffffffffu, s1, 16);
                ADD2(v0, k0, r0);
                ADD2(v1, k1, r1);
            }
            u64 w;
            {
                u64 sv = hi8 ? v0 : v1;
                u64 kv = hi8 ? v1 : v0;
                u64 rv = __shfl_xor_sync(0xffffffffu, sv, 8);
                ADD2(w, kv, rv);
            }
            {
                u64 rv = __shfl_xor_sync(0xffffffffu, w, 4);
                ADD2(w, w, rv);
                rv = __shfl_xor_sync(0xffffffffu, w, 2);
                ADD2(w, w, rv);
                rv = __shfl_xor_sync(0xffffffffu, w, 1);
                ADD2(w, w, rv);
            }
            if ((lane & 7) == 0) {
                const int p = lane >> 3;
                *reinterpret_cast<u64*>(&s_part[s * SROWS + r][warp][2 * p]) = w;
            }
        }
        __syncthreads();   // slot drained; s_part row-group committed

        if (tid == 0 && s + NSLOT < nstage) {
            mbar_expect_tx(mb0 + slot * 8, STBYTES);
            bulk_g2s(xs0 + slot * STBYTES,
                     src + (size_t)(s + NSLOT) * SROWS * E_DIM,
                     STBYTES, mb0 + slot * 8);
        }
    }

    // ---- [B] q epilogue: nrows x 8 f <= 448 items, 2 per thread ----
#pragma unroll
    for (int it = 0; it < 2; it++) {
        const int item  = it * 256 + tid;
        const bool valid = item < nrows * 8;
        const int r  = valid ? (item >> 3) : 0;
        const int ff = item & 7;          // == tid & 7, matches bf

        float h = bf;
#pragma unroll
        for (int w = 0; w < 8; w++) h += s_part[r][w][ff];
        float c = __cosf(h);

        // all lanes participate in the shfl (inactive lanes carry junk)
        const int base = lane & 24;
        float cs[8];
#pragma unroll
        for (int jj = 0; jj < 8; jj++)
            cs[jj] = __shfl_sync(0xffffffffu, c, base + jj);

        float q;
        if (ff == 7) {
            q = cs[0]*cs[1]*cs[2]*cs[3]*cs[4]*cs[5]*cs[6]*cs[7];
        } else {
            q = 1.0f;
#pragma unroll
            for (int jj = 0; jj < 8; jj++)
                if (jj <= ff && ((jj ^ ff) & 1) == 0) q *= cs[jj];
        }
        if (valid) s_q[r][ff] = q;
    }
    __syncthreads();

    // ---- [C] out tail: w2 f-pairs in regs (loaded after w1 regs die) ----
    const int e2 = tid * 4;
    u64 wp[4][4];
#pragma unroll
    for (int i = 0; i < 4; i++) {
        ulonglong2 v0 = *reinterpret_cast<const ulonglong2*>(w2 + (e2 + i) * 8);
        ulonglong2 v1 = *reinterpret_cast<const ulonglong2*>(w2 + (e2 + i) * 8 + 4);
        wp[i][0] = v0.x; wp[i][1] = v0.y;
        wp[i][2] = v1.x; wp[i][3] = v1.y;
    }
    u64 binit[4];
    {
        float4 bv = *reinterpret_cast<const float4*>(b2 + e2);
        binit[0] = pack2(bv.x, 0.f);
        binit[1] = pack2(bv.y, 0.f);
        binit[2] = pack2(bv.z, 0.f);
        binit[3] = pack2(bv.w, 0.f);
    }

    float* orow = out + (size_t)block_row0 * E_DIM + e2;
#pragma unroll 4
    for (int r = 0; r < nrows; r++) {
        ulonglong2 qv0 = *reinterpret_cast<const ulonglong2*>(&s_q[r][0]);
        ulonglong2 qv1 = *reinterpret_cast<const ulonglong2*>(&s_q[r][4]);

        float o[4];
#pragma unroll
        for (int i = 0; i < 4; i++) {
            u64 acc = binit[i];
            FMA2(acc, qv0.x, wp[i][0], acc);
            FMA2(acc, qv0.y, wp[i][1], acc);
            FMA2(acc, qv1.x, wp[i][2], acc);
            FMA2(acc, qv1.y, wp[i][3], acc);
            float2 t = unpack2(acc);
            o[i] = t.x + t.y;
        }
        stg_cs_v4(orow, make_float4(o[0], o[1], o[2], o[3]));
        orow += E_DIM;
    }
}

extern "C" void kernel_launch(void* const* d_in, const int* in_sizes, int n_in,
                              void* d_out, int out_size) {
    const float* x  = (const float*)d_in[0];
    const float* w1 = (const float*)d_in[1];
    const float* b1 = (const float*)d_in[2];
    const float* w2 = (const float*)d_in[3];
    const float* b2 = (const float*)d_in[4];
    float* out = (float*)d_out;

    int nsm = 148;
    cudaDeviceGetAttribute(&nsm, cudaDevAttrMultiProcessorCount, 0);
    const int grid = 4 * nsm;                    // one CTA per residency slot

    const int rows    = in_sizes[0] / E_DIM;     // 32768
    const int ngroups = rows / SROWS;            // 8192 four-row groups
    ffq_fused<<<grid, 256>>>(x, w1, b1, w2, b2, out, ngroups);
}